// round 1
// baseline (speedup 1.0000x reference)
#include <cuda_runtime.h>
#include <math.h>

// Problem dims (fixed by the reference)
#define BB 8
#define SS 2048
#define EE 512
#define HH 8
#define DD 64
#define BS (BB*SS)          // 16384 rows

// Scratch: q,k,v,att in [B,H,S,D] layout (32 MiB each)
__device__ float g_q[BB*HH*SS*DD];
__device__ float g_k[BB*HH*SS*DD];
__device__ float g_v[BB*HH*SS*DD];
__device__ float g_att[BB*HH*SS*DD];

// ---------------------------------------------------------------------------
// Kernel 1: fused QKV projection.
// q[b,h,s,d] = sum_e x[b,s,e] * Wq[h,e,d]   (same for k,v)
// GEMM view: M = B*S = 16384 rows of x, per head N = 64, K = 512.
// Tiles: BM=128, BN=64 (one head), BK=16. 256 threads, 8x4 per thread,
// three accumulator sets (q,k,v) sharing the X fragment (FMA:LDS = 4.8:1).
// ---------------------------------------------------------------------------
__global__ __launch_bounds__(256, 1)
void qkv_kernel(const float* __restrict__ x,
                const float* __restrict__ Wq,
                const float* __restrict__ Wk,
                const float* __restrict__ Wv)
{
    const int h  = blockIdx.x;           // head (N tile)
    const int m0 = blockIdx.y * 128;     // row tile
    const int tid = threadIdx.x;
    const int tx = tid & 15;             // 16 -> 64 cols
    const int ty = tid >> 4;             // 16 -> 128 rows
    const int r0 = ty * 8;
    const int c0 = tx * 4;

    __shared__ float Xt[16][132];        // transposed: [k][m]
    __shared__ float Wqs[16][68], Wks[16][68], Wvs[16][68];

    float cq[8][4], ck[8][4], cv[8][4];
    #pragma unroll
    for (int i = 0; i < 8; i++)
        #pragma unroll
        for (int j = 0; j < 4; j++) { cq[i][j]=0.f; ck[i][j]=0.f; cv[i][j]=0.f; }

    const float* wq = Wq + (size_t)h * EE * DD;
    const float* wk = Wk + (size_t)h * EE * DD;
    const float* wv = Wv + (size_t)h * EE * DD;

    for (int k0 = 0; k0 < EE; k0 += 16) {
        // X tile 128x16 -> transposed smem. 512 float4 loads / 256 threads.
        {
            const int m = tid >> 1;
            #pragma unroll
            for (int it = 0; it < 2; it++) {
                const int kc = ((tid & 1) << 1) + it;       // 0..3
                float4 g = *(const float4*)&x[(size_t)(m0 + m) * EE + k0 + kc * 4];
                Xt[kc*4+0][m] = g.x; Xt[kc*4+1][m] = g.y;
                Xt[kc*4+2][m] = g.z; Xt[kc*4+3][m] = g.w;
            }
        }
        // Weight tiles 16x64 each: exactly 256 float4 per tensor.
        {
            const int kk = tid >> 4;
            const int n0 = (tid & 15) * 4;
            *(float4*)&Wqs[kk][n0] = *(const float4*)&wq[(size_t)(k0 + kk) * DD + n0];
            *(float4*)&Wks[kk][n0] = *(const float4*)&wk[(size_t)(k0 + kk) * DD + n0];
            *(float4*)&Wvs[kk][n0] = *(const float4*)&wv[(size_t)(k0 + kk) * DD + n0];
        }
        __syncthreads();

        #pragma unroll
        for (int kk = 0; kk < 16; kk++) {
            float a[8];
            float4 a0 = *(const float4*)&Xt[kk][r0];
            float4 a1 = *(const float4*)&Xt[kk][r0 + 4];
            a[0]=a0.x; a[1]=a0.y; a[2]=a0.z; a[3]=a0.w;
            a[4]=a1.x; a[5]=a1.y; a[6]=a1.z; a[7]=a1.w;
            float4 bq = *(const float4*)&Wqs[kk][c0];
            float4 bk = *(const float4*)&Wks[kk][c0];
            float4 bv = *(const float4*)&Wvs[kk][c0];
            const float bqa[4] = {bq.x, bq.y, bq.z, bq.w};
            const float bka[4] = {bk.x, bk.y, bk.z, bk.w};
            const float bva[4] = {bv.x, bv.y, bv.z, bv.w};
            #pragma unroll
            for (int i = 0; i < 8; i++)
                #pragma unroll
                for (int j = 0; j < 4; j++) {
                    cq[i][j] += a[i] * bqa[j];
                    ck[i][j] += a[i] * bka[j];
                    cv[i][j] += a[i] * bva[j];
                }
        }
        __syncthreads();
    }

    // Write out in [B,H,S,D]
    #pragma unroll
    for (int i = 0; i < 8; i++) {
        const int m = m0 + r0 + i;
        const int b = m / SS, s = m % SS;
        const size_t base = (((size_t)(b * HH + h)) * SS + s) * DD + c0;
        *(float4*)&g_q[base] = make_float4(cq[i][0], cq[i][1], cq[i][2], cq[i][3]);
        *(float4*)&g_k[base] = make_float4(ck[i][0], ck[i][1], ck[i][2], ck[i][3]);
        *(float4*)&g_v[base] = make_float4(cv[i][0], cv[i][1], cv[i][2], cv[i][3]);
    }
}

// ---------------------------------------------------------------------------
// Kernel 2: flash attention (fp32, causal, online softmax).
// Q tile: 128 rows x D=64.  K/V tiles: 64 rows.  256 threads, 8x4 per thread.
// Only lower-triangular tiles are processed (skips ~47% of the work).
// ---------------------------------------------------------------------------
#define ATT_SMEM_FLOATS (128*68 + 64*68 + 64*68 + 128*68)
#define ATT_SMEM_BYTES  (ATT_SMEM_FLOATS * 4)

__global__ __launch_bounds__(256, 2)
void attn_kernel()
{
    extern __shared__ float sm[];
    float (*Qs)[68] = (float(*)[68])(sm);                       // 128 x 68
    float (*Kt)[68] = (float(*)[68])(sm + 128*68);              // 64 x 68 (d-major)
    float (*Vs)[68] = (float(*)[68])(sm + 128*68 + 64*68);      // 64 x 68
    float (*Ps)[68] = (float(*)[68])(sm + 128*68 + 2*64*68);    // 128 x 68

    const int qt = (gridDim.x - 1) - blockIdx.x;   // heavy q-tiles launch first
    const int bh = blockIdx.y;
    const int tid = threadIdx.x;
    const int tx = tid & 15;
    const int ty = tid >> 4;
    const int r0 = ty * 8;       // 8 q-rows per thread
    const int c0 = tx * 4;       // 4 k-cols per thread

    const float* Qg = g_q + (size_t)bh * SS * DD;
    const float* Kg = g_k + (size_t)bh * SS * DD;
    const float* Vg = g_v + (size_t)bh * SS * DD;

    // Load Q tile (128x64): 8 float4 per thread.
    {
        const int row = tid >> 1;
        const int dbase = (tid & 1) * 32;
        #pragma unroll
        for (int it = 0; it < 8; it++) {
            const int d0 = dbase + it * 4;
            *(float4*)&Qs[row][d0] =
                *(const float4*)&Qg[(size_t)(qt * 128 + row) * DD + d0];
        }
    }

    float o[8][4];
    float mrow[8], lrow[8];
    #pragma unroll
    for (int i = 0; i < 8; i++) {
        mrow[i] = -1e30f; lrow[i] = 0.f;
        #pragma unroll
        for (int j = 0; j < 4; j++) o[i][j] = 0.f;
    }

    const int njt = 2 * qt + 2;     // causal: k-tiles 0 .. 2*qt+1
    for (int jt = 0; jt < njt; jt++) {
        __syncthreads();            // prior iteration done with Kt/Vs/Ps
        // Load K (transposed -> Kt[d][c]) and V (Vs[t][d]): 4 float4 each.
        {
            const int row = tid >> 2;
            #pragma unroll
            for (int it = 0; it < 4; it++) {
                const int d0 = (tid & 3) * 16 + it * 4;
                float4 kv = *(const float4*)&Kg[(size_t)(jt * 64 + row) * DD + d0];
                Kt[d0+0][row] = kv.x; Kt[d0+1][row] = kv.y;
                Kt[d0+2][row] = kv.z; Kt[d0+3][row] = kv.w;
                *(float4*)&Vs[row][d0] =
                    *(const float4*)&Vg[(size_t)(jt * 64 + row) * DD + d0];
            }
        }
        __syncthreads();

        // S = Q @ K^T  (8x4 per thread, K-dim 64)
        float sacc[8][4];
        #pragma unroll
        for (int i = 0; i < 8; i++)
            #pragma unroll
            for (int j = 0; j < 4; j++) sacc[i][j] = 0.f;

        #pragma unroll 4
        for (int d = 0; d < 64; d++) {
            float a[8];
            #pragma unroll
            for (int i = 0; i < 8; i++) a[i] = Qs[r0 + i][d];
            float4 bv = *(const float4*)&Kt[d][c0];
            const float bb[4] = {bv.x, bv.y, bv.z, bv.w};
            #pragma unroll
            for (int i = 0; i < 8; i++)
                #pragma unroll
                for (int j = 0; j < 4; j++) sacc[i][j] += a[i] * bb[j];
        }

        // scale + causal mask (only the two diagonal-straddling tiles need it)
        const bool diag = (jt >= 2 * qt);
        #pragma unroll
        for (int i = 0; i < 8; i++) {
            const int row_g = qt * 128 + r0 + i;
            #pragma unroll
            for (int j = 0; j < 4; j++) {
                float v = sacc[i][j] * 0.125f;    // 1/sqrt(64)
                if (diag && (jt * 64 + c0 + j > row_g)) v = -1e30f;
                sacc[i][j] = v;
            }
        }

        // Online softmax update per row (reduce across the 16 tx lanes)
        #pragma unroll
        for (int i = 0; i < 8; i++) {
            float rmax = fmaxf(fmaxf(sacc[i][0], sacc[i][1]),
                               fmaxf(sacc[i][2], sacc[i][3]));
            #pragma unroll
            for (int off = 8; off > 0; off >>= 1)
                rmax = fmaxf(rmax, __shfl_xor_sync(0xffffffffu, rmax, off));

            const float mnew = fmaxf(mrow[i], rmax);
            const float corr = __expf(mrow[i] - mnew);

            float p0 = __expf(sacc[i][0] - mnew);
            float p1 = __expf(sacc[i][1] - mnew);
            float p2 = __expf(sacc[i][2] - mnew);
            float p3 = __expf(sacc[i][3] - mnew);
            float psum = p0 + p1 + p2 + p3;
            #pragma unroll
            for (int off = 8; off > 0; off >>= 1)
                psum += __shfl_xor_sync(0xffffffffu, psum, off);

            lrow[i] = lrow[i] * corr + psum;
            mrow[i] = mnew;
            #pragma unroll
            for (int j = 0; j < 4; j++) o[i][j] *= corr;

            *(float4*)&Ps[r0 + i][c0] = make_float4(p0, p1, p2, p3);
        }
        __syncthreads();

        // O += P @ V
        #pragma unroll 4
        for (int t = 0; t < 64; t++) {
            float a[8];
            #pragma unroll
            for (int i = 0; i < 8; i++) a[i] = Ps[r0 + i][t];
            float4 bv = *(const float4*)&Vs[t][c0];
            const float bb[4] = {bv.x, bv.y, bv.z, bv.w};
            #pragma unroll
            for (int i = 0; i < 8; i++)
                #pragma unroll
                for (int j = 0; j < 4; j++) o[i][j] += a[i] * bb[j];
        }
    }

    // Normalize and store
    float* Og = g_att + (size_t)bh * SS * DD;
    #pragma unroll
    for (int i = 0; i < 8; i++) {
        const float inv = 1.f / lrow[i];
        const int row = qt * 128 + r0 + i;
        *(float4*)&Og[(size_t)row * DD + c0] =
            make_float4(o[i][0]*inv, o[i][1]*inv, o[i][2]*inv, o[i][3]*inv);
    }
}

// ---------------------------------------------------------------------------
// Kernel 3: output projection. out[b,s,:] = att_concat[b,s,:] @ Wp + bp
// A rows are gathered from [B,H,S,D] scratch (head = k/64).
// BM=128, BN=64, BK=16, 256 threads, 8x4 per thread.
// ---------------------------------------------------------------------------
__global__ __launch_bounds__(256, 2)
void proj_kernel(const float* __restrict__ Wp,
                 const float* __restrict__ bp,
                 float* __restrict__ out)
{
    const int n0t = blockIdx.x * 64;
    const int m0  = blockIdx.y * 128;
    const int tid = threadIdx.x;
    const int tx = tid & 15, ty = tid >> 4;
    const int r0 = ty * 8, c0 = tx * 4;

    __shared__ float At[16][132];   // transposed: [k][m]
    __shared__ float Ws[16][68];

    float acc[8][4];
    #pragma unroll
    for (int i = 0; i < 8; i++)
        #pragma unroll
        for (int j = 0; j < 4; j++) acc[i][j] = 0.f;

    for (int k0 = 0; k0 < EE; k0 += 16) {
        const int h    = k0 >> 6;       // head for this K tile (16 | 64)
        const int coff = k0 & 63;
        // A tile: rows m0..+127, k-slice from g_att ([B,H,S,D] gather)
        {
            const int m = tid >> 1;
            const int mm = m0 + m;
            const int b = mm / SS, s = mm % SS;
            const size_t abase = (((size_t)(b * HH + h)) * SS + s) * DD + coff;
            #pragma unroll
            for (int it = 0; it < 2; it++) {
                const int kc = ((tid & 1) << 1) + it;
                float4 g = *(const float4*)&g_att[abase + kc * 4];
                At[kc*4+0][m] = g.x; At[kc*4+1][m] = g.y;
                At[kc*4+2][m] = g.z; At[kc*4+3][m] = g.w;
            }
        }
        // Wp tile
        {
            const int kk = tid >> 4;
            const int n0 = (tid & 15) * 4;
            *(float4*)&Ws[kk][n0] = *(const float4*)&Wp[(size_t)(k0 + kk) * EE + n0t + n0];
        }
        __syncthreads();

        #pragma unroll
        for (int kk = 0; kk < 16; kk++) {
            float a[8];
            float4 a0 = *(const float4*)&At[kk][r0];
            float4 a1 = *(const float4*)&At[kk][r0 + 4];
            a[0]=a0.x; a[1]=a0.y; a[2]=a0.z; a[3]=a0.w;
            a[4]=a1.x; a[5]=a1.y; a[6]=a1.z; a[7]=a1.w;
            float4 bv = *(const float4*)&Ws[kk][c0];
            const float bb[4] = {bv.x, bv.y, bv.z, bv.w};
            #pragma unroll
            for (int i = 0; i < 8; i++)
                #pragma unroll
                for (int j = 0; j < 4; j++) acc[i][j] += a[i] * bb[j];
        }
        __syncthreads();
    }

    float4 bias = *(const float4*)&bp[n0t + c0];
    const float ba[4] = {bias.x, bias.y, bias.z, bias.w};
    #pragma unroll
    for (int i = 0; i < 8; i++) {
        const int m = m0 + r0 + i;
        *(float4*)&out[(size_t)m * EE + n0t + c0] =
            make_float4(acc[i][0]+ba[0], acc[i][1]+ba[1],
                        acc[i][2]+ba[2], acc[i][3]+ba[3]);
    }
}

// ---------------------------------------------------------------------------
extern "C" void kernel_launch(void* const* d_in, const int* in_sizes, int n_in,
                              void* d_out, int out_size)
{
    const float* x  = (const float*)d_in[0];
    const float* Wq = (const float*)d_in[1];
    const float* Wk = (const float*)d_in[2];
    const float* Wv = (const float*)d_in[3];
    const float* Wp = (const float*)d_in[4];
    const float* bp = (const float*)d_in[5];
    float* out = (float*)d_out;

    (void)in_sizes; (void)n_in; (void)out_size;

    // 1) fused QKV projection
    qkv_kernel<<<dim3(HH, BS / 128), 256>>>(x, Wq, Wk, Wv);

    // 2) flash attention (opt-in to >48KB dynamic smem; not a stream op,
    //    safe under graph capture)
    cudaFuncSetAttribute(attn_kernel,
                         cudaFuncAttributeMaxDynamicSharedMemorySize,
                         ATT_SMEM_BYTES);
    attn_kernel<<<dim3(SS / 128, BB * HH), 256, ATT_SMEM_BYTES>>>();

    // 3) output projection + bias
    proj_kernel<<<dim3(EE / 64, BS / 128), 256>>>(Wp, bp, out);
}

// round 5
// speedup vs baseline: 1.3533x; 1.3533x over previous
#include <cuda_runtime.h>
#include <cstdint>
#include <math.h>

// Problem dims (fixed by the reference)
#define BB 8
#define SS 2048
#define EE 512
#define HH 8
#define DD 64
#define BS (BB*SS)          // 16384 rows

// Scratch: q,k,v,att in [B,H,S,D] layout (32 MiB each)
__device__ float g_q[BB*HH*SS*DD];
__device__ float g_k[BB*HH*SS*DD];
__device__ float g_v[BB*HH*SS*DD];
__device__ float g_att[BB*HH*SS*DD];

static __device__ __forceinline__ uint32_t cvt_tf32(float f) {
    uint32_t r; asm("cvt.rna.tf32.f32 %0, %1;" : "=r"(r) : "f"(f)); return r;
}

// m16n8k8 tf32 mma.sync (baseline PTX — no sm_103a-only features)
#define MMA_TF32(c, a, b) \
    asm volatile("mma.sync.aligned.m16n8k8.row.col.f32.tf32.tf32.f32 " \
        "{%0,%1,%2,%3}, {%4,%5,%6,%7}, {%8,%9}, {%0,%1,%2,%3};" \
        : "+f"((c)[0]), "+f"((c)[1]), "+f"((c)[2]), "+f"((c)[3]) \
        : "r"((a)[0]), "r"((a)[1]), "r"((a)[2]), "r"((a)[3]), \
          "r"((b)[0]), "r"((b)[1]))

// ===========================================================================
// Kernel 1: fused QKV projection via mma.sync tf32.
// Per CTA: one head h, 128 M-rows, N=192 (q|k|v concatenated), K=512 in
// BK=32 chunks.  8 warps as 2(M)x4(N): warp tile 64x48 = 4 m16 x 6 n8.
// Smem: Xs[row][k] stride 36 (A-frag LDS conflict-free: banks 4g+tig),
//       Ws[k][n]  stride 200 (B-frag LDS conflict-free: banks 8tig+g).
// ===========================================================================
__global__ __launch_bounds__(256, 1)
void qkv_mma_kernel(const float* __restrict__ x,
                    const float* __restrict__ Wq,
                    const float* __restrict__ Wk,
                    const float* __restrict__ Wv)
{
    __shared__ uint32_t Xs[128 * 36];     // 18432 B
    __shared__ uint32_t Ws[32 * 200];     // 25600 B

    const int tid  = threadIdx.x;
    const int wid  = tid >> 5;
    const int lane = tid & 31;
    const int h  = blockIdx.x;
    const int m0 = blockIdx.y * 128;
    const int wm = wid >> 2;              // 0..1
    const int wn = wid & 3;               // 0..3
    const int g   = lane >> 2;            // 0..7
    const int tig = lane & 3;             // 0..3

    const float* Wt0 = Wq + (size_t)h * EE * DD;
    const float* Wt1 = Wk + (size_t)h * EE * DD;
    const float* Wt2 = Wv + (size_t)h * EE * DD;

    float acc[4][6][4];
    #pragma unroll
    for (int mi = 0; mi < 4; mi++)
        #pragma unroll
        for (int ni = 0; ni < 6; ni++)
            #pragma unroll
            for (int j = 0; j < 4; j++) acc[mi][ni][j] = 0.f;

    for (int c = 0; c < 16; c++) {
        const int k0 = c * 32;
        __syncthreads();
        // X tile: 128 rows x 32 k -> Xs[row][k], 4 float4 per thread.
        #pragma unroll
        for (int i = 0; i < 4; i++) {
            const int idx = tid + 256 * i;
            const int row = idx >> 3, c4 = idx & 7;
            float4 gv = *(const float4*)&x[(size_t)(m0 + row) * EE + k0 + c4 * 4];
            uint4 t;
            t.x = cvt_tf32(gv.x); t.y = cvt_tf32(gv.y);
            t.z = cvt_tf32(gv.z); t.w = cvt_tf32(gv.w);
            *(uint4*)&Xs[row * 36 + c4 * 4] = t;
        }
        // W tiles: W[e][d] -> Ws[k=e][n=t*64+d], 6 float4 per thread.
        #pragma unroll
        for (int i = 0; i < 6; i++) {
            const int idx = tid + 256 * i;
            const int t  = idx >> 9;            // 0..2 (tensor)
            const int rem = idx & 511;
            const int e  = rem >> 4;            // 0..31
            const int d4 = rem & 15;            // 0..15
            const float* Wp = (t == 0) ? Wt0 : (t == 1) ? Wt1 : Wt2;
            float4 gv = *(const float4*)&Wp[(size_t)(k0 + e) * DD + d4 * 4];
            uint4 tt;
            tt.x = cvt_tf32(gv.x); tt.y = cvt_tf32(gv.y);
            tt.z = cvt_tf32(gv.z); tt.w = cvt_tf32(gv.w);
            *(uint4*)&Ws[e * 200 + t * 64 + d4 * 4] = tt;
        }
        __syncthreads();

        #pragma unroll
        for (int s = 0; s < 4; s++) {
            const int kk = s * 8;
            uint32_t a[4][4];
            #pragma unroll
            for (int mi = 0; mi < 4; mi++) {
                const int mb = wm * 64 + mi * 16;
                a[mi][0] = Xs[(mb + g    ) * 36 + kk + tig];
                a[mi][1] = Xs[(mb + g + 8) * 36 + kk + tig];
                a[mi][2] = Xs[(mb + g    ) * 36 + kk + tig + 4];
                a[mi][3] = Xs[(mb + g + 8) * 36 + kk + tig + 4];
            }
            uint32_t b[6][2];
            #pragma unroll
            for (int ni = 0; ni < 6; ni++) {
                const int nb = wn * 48 + ni * 8;
                b[ni][0] = Ws[(kk + tig    ) * 200 + nb + g];
                b[ni][1] = Ws[(kk + tig + 4) * 200 + nb + g];
            }
            #pragma unroll
            for (int mi = 0; mi < 4; mi++)
                #pragma unroll
                for (int ni = 0; ni < 6; ni++)
                    MMA_TF32(acc[mi][ni], a[mi], b[ni]);
        }
    }

    // Epilogue: scatter to g_q / g_k / g_v ([B,H,S,D])
    #pragma unroll
    for (int mi = 0; mi < 4; mi++) {
        const int m1 = m0 + wm * 64 + mi * 16 + g;
        const int b = m1 >> 11, s1 = m1 & 2047;
        #pragma unroll
        for (int ni = 0; ni < 6; ni++) {
            const int colg = wn * 48 + ni * 8 + 2 * tig;
            const int tt = colg >> 6;
            const int d  = colg & 63;
            float* dst = (tt == 0) ? g_q : (tt == 1) ? g_k : g_v;
            const size_t base = (((size_t)(b * HH + h)) * SS + s1) * DD + d;
            *(float2*)&dst[base] = make_float2(acc[mi][ni][0], acc[mi][ni][1]);
            *(float2*)&dst[base + 8 * DD] = make_float2(acc[mi][ni][2], acc[mi][ni][3]);
        }
    }
}

// ===========================================================================
// Kernel 2: flash attention (fp32, causal, online softmax) — unchanged.
// ===========================================================================
#define ATT_SMEM_FLOATS (128*68 + 64*68 + 64*68 + 128*68)
#define ATT_SMEM_BYTES  (ATT_SMEM_FLOATS * 4)

__global__ __launch_bounds__(256, 2)
void attn_kernel()
{
    extern __shared__ float smf[];
    float (*Qs)[68] = (float(*)[68])(smf);
    float (*Kt)[68] = (float(*)[68])(smf + 128*68);
    float (*Vs)[68] = (float(*)[68])(smf + 128*68 + 64*68);
    float (*Ps)[68] = (float(*)[68])(smf + 128*68 + 2*64*68);

    const int qt = (gridDim.x - 1) - blockIdx.x;
    const int bh = blockIdx.y;
    const int tid = threadIdx.x;
    const int tx = tid & 15;
    const int ty = tid >> 4;
    const int r0 = ty * 8;
    const int c0 = tx * 4;

    const float* Qg = g_q + (size_t)bh * SS * DD;
    const float* Kg = g_k + (size_t)bh * SS * DD;
    const float* Vg = g_v + (size_t)bh * SS * DD;

    {
        const int row = tid >> 1;
        const int dbase = (tid & 1) * 32;
        #pragma unroll
        for (int it = 0; it < 8; it++) {
            const int d0 = dbase + it * 4;
            *(float4*)&Qs[row][d0] =
                *(const float4*)&Qg[(size_t)(qt * 128 + row) * DD + d0];
        }
    }

    float o[8][4];
    float mrow[8], lrow[8];
    #pragma unroll
    for (int i = 0; i < 8; i++) {
        mrow[i] = -1e30f; lrow[i] = 0.f;
        #pragma unroll
        for (int j = 0; j < 4; j++) o[i][j] = 0.f;
    }

    const int njt = 2 * qt + 2;
    for (int jt = 0; jt < njt; jt++) {
        __syncthreads();
        {
            const int row = tid >> 2;
            #pragma unroll
            for (int it = 0; it < 4; it++) {
                const int d0 = (tid & 3) * 16 + it * 4;
                float4 kv = *(const float4*)&Kg[(size_t)(jt * 64 + row) * DD + d0];
                Kt[d0+0][row] = kv.x; Kt[d0+1][row] = kv.y;
                Kt[d0+2][row] = kv.z; Kt[d0+3][row] = kv.w;
                *(float4*)&Vs[row][d0] =
                    *(const float4*)&Vg[(size_t)(jt * 64 + row) * DD + d0];
            }
        }
        __syncthreads();

        float sacc[8][4];
        #pragma unroll
        for (int i = 0; i < 8; i++)
            #pragma unroll
            for (int j = 0; j < 4; j++) sacc[i][j] = 0.f;

        #pragma unroll 4
        for (int d = 0; d < 64; d++) {
            float a[8];
            #pragma unroll
            for (int i = 0; i < 8; i++) a[i] = Qs[r0 + i][d];
            float4 bv = *(const float4*)&Kt[d][c0];
            const float bb[4] = {bv.x, bv.y, bv.z, bv.w};
            #pragma unroll
            for (int i = 0; i < 8; i++)
                #pragma unroll
                for (int j = 0; j < 4; j++) sacc[i][j] += a[i] * bb[j];
        }

        const bool diag = (jt >= 2 * qt);
        #pragma unroll
        for (int i = 0; i < 8; i++) {
            const int row_g = qt * 128 + r0 + i;
            #pragma unroll
            for (int j = 0; j < 4; j++) {
                float v = sacc[i][j] * 0.125f;
                if (diag && (jt * 64 + c0 + j > row_g)) v = -1e30f;
                sacc[i][j] = v;
            }
        }

        #pragma unroll
        for (int i = 0; i < 8; i++) {
            float rmax = fmaxf(fmaxf(sacc[i][0], sacc[i][1]),
                               fmaxf(sacc[i][2], sacc[i][3]));
            #pragma unroll
            for (int off = 8; off > 0; off >>= 1)
                rmax = fmaxf(rmax, __shfl_xor_sync(0xffffffffu, rmax, off));

            const float mnew = fmaxf(mrow[i], rmax);
            const float corr = __expf(mrow[i] - mnew);

            float p0 = __expf(sacc[i][0] - mnew);
            float p1 = __expf(sacc[i][1] - mnew);
            float p2 = __expf(sacc[i][2] - mnew);
            float p3 = __expf(sacc[i][3] - mnew);
            float psum = p0 + p1 + p2 + p3;
            #pragma unroll
            for (int off = 8; off > 0; off >>= 1)
                psum += __shfl_xor_sync(0xffffffffu, psum, off);

            lrow[i] = lrow[i] * corr + psum;
            mrow[i] = mnew;
            #pragma unroll
            for (int j = 0; j < 4; j++) o[i][j] *= corr;

            *(float4*)&Ps[r0 + i][c0] = make_float4(p0, p1, p2, p3);
        }
        __syncthreads();

        #pragma unroll 4
        for (int t = 0; t < 64; t++) {
            float a[8];
            #pragma unroll
            for (int i = 0; i < 8; i++) a[i] = Ps[r0 + i][t];
            float4 bv = *(const float4*)&Vs[t][c0];
            const float bb[4] = {bv.x, bv.y, bv.z, bv.w};
            #pragma unroll
            for (int i = 0; i < 8; i++)
                #pragma unroll
                for (int j = 0; j < 4; j++) o[i][j] += a[i] * bb[j];
        }
    }

    float* Og = g_att + (size_t)bh * SS * DD;
    #pragma unroll
    for (int i = 0; i < 8; i++) {
        const float inv = 1.f / lrow[i];
        const int row = qt * 128 + r0 + i;
        *(float4*)&Og[(size_t)row * DD + c0] =
            make_float4(o[i][0]*inv, o[i][1]*inv, o[i][2]*inv, o[i][3]*inv);
    }
}

// ===========================================================================
// Kernel 3: output projection via mma.sync tf32.
// Per CTA: 128 M x 128 N, K=512 in BK=32 chunks.  8 warps as 2(M)x4(N):
// warp tile 64x32 = 4 m16 x 4 n8.
// ===========================================================================
__global__ __launch_bounds__(256, 2)
void proj_mma_kernel(const float* __restrict__ Wp,
                     const float* __restrict__ bp,
                     float* __restrict__ out)
{
    __shared__ uint32_t Xs[128 * 36];     // 18432 B (A rows)
    __shared__ uint32_t Bs[32 * 136];     // 17408 B (Wp: [k][n])

    const int tid  = threadIdx.x;
    const int wid  = tid >> 5;
    const int lane = tid & 31;
    const int n0 = blockIdx.x * 128;
    const int m0 = blockIdx.y * 128;
    const int wm = wid >> 2;
    const int wn = wid & 3;
    const int g   = lane >> 2;
    const int tig = lane & 3;

    float acc[4][4][4];
    #pragma unroll
    for (int mi = 0; mi < 4; mi++)
        #pragma unroll
        for (int ni = 0; ni < 4; ni++)
            #pragma unroll
            for (int j = 0; j < 4; j++) acc[mi][ni][j] = 0.f;

    for (int c = 0; c < 16; c++) {
        const int k0 = c * 32;
        const int h = k0 >> 6;            // head for this K chunk (32 | 64)
        const int coff = k0 & 63;
        __syncthreads();
        // A tile from g_att gather: rows m0..+127, k-cols k0..+31
        #pragma unroll
        for (int i = 0; i < 4; i++) {
            const int idx = tid + 256 * i;
            const int row = idx >> 3, c4 = idx & 7;
            const int mm = m0 + row;
            const int b = mm >> 11, s = mm & 2047;
            float4 gv = *(const float4*)
                &g_att[(((size_t)(b * HH + h)) * SS + s) * DD + coff + c4 * 4];
            uint4 t;
            t.x = cvt_tf32(gv.x); t.y = cvt_tf32(gv.y);
            t.z = cvt_tf32(gv.z); t.w = cvt_tf32(gv.w);
            *(uint4*)&Xs[row * 36 + c4 * 4] = t;
        }
        // B tile: Wp[e][n] -> Bs[k=e][n], 4 float4 per thread.
        #pragma unroll
        for (int i = 0; i < 4; i++) {
            const int idx = tid + 256 * i;
            const int e  = idx >> 5;          // 0..31
            const int n4 = idx & 31;          // 0..31
            float4 gv = *(const float4*)&Wp[(size_t)(k0 + e) * EE + n0 + n4 * 4];
            uint4 t;
            t.x = cvt_tf32(gv.x); t.y = cvt_tf32(gv.y);
            t.z = cvt_tf32(gv.z); t.w = cvt_tf32(gv.w);
            *(uint4*)&Bs[e * 136 + n4 * 4] = t;
        }
        __syncthreads();

        #pragma unroll
        for (int s = 0; s < 4; s++) {
            const int kk = s * 8;
            uint32_t a[4][4];
            #pragma unroll
            for (int mi = 0; mi < 4; mi++) {
                const int mb = wm * 64 + mi * 16;
                a[mi][0] = Xs[(mb + g    ) * 36 + kk + tig];
                a[mi][1] = Xs[(mb + g + 8) * 36 + kk + tig];
                a[mi][2] = Xs[(mb + g    ) * 36 + kk + tig + 4];
                a[mi][3] = Xs[(mb + g + 8) * 36 + kk + tig + 4];
            }
            uint32_t b[4][2];
            #pragma unroll
            for (int ni = 0; ni < 4; ni++) {
                const int nb = wn * 32 + ni * 8;
                b[ni][0] = Bs[(kk + tig    ) * 136 + nb + g];
                b[ni][1] = Bs[(kk + tig + 4) * 136 + nb + g];
            }
            #pragma unroll
            for (int mi = 0; mi < 4; mi++)
                #pragma unroll
                for (int ni = 0; ni < 4; ni++)
                    MMA_TF32(acc[mi][ni], a[mi], b[ni]);
        }
    }

    // Epilogue: bias + store
    #pragma unroll
    for (int mi = 0; mi < 4; mi++) {
        const int m1 = m0 + wm * 64 + mi * 16 + g;
        #pragma unroll
        for (int ni = 0; ni < 4; ni++) {
            const int col = n0 + wn * 32 + ni * 8 + 2 * tig;
            float2 bias = *(const float2*)&bp[col];
            *(float2*)&out[(size_t)m1 * EE + col] =
                make_float2(acc[mi][ni][0] + bias.x, acc[mi][ni][1] + bias.y);
            *(float2*)&out[(size_t)(m1 + 8) * EE + col] =
                make_float2(acc[mi][ni][2] + bias.x, acc[mi][ni][3] + bias.y);
        }
    }
}

// ---------------------------------------------------------------------------
extern "C" void kernel_launch(void* const* d_in, const int* in_sizes, int n_in,
                              void* d_out, int out_size)
{
    const float* x  = (const float*)d_in[0];
    const float* Wq = (const float*)d_in[1];
    const float* Wk = (const float*)d_in[2];
    const float* Wv = (const float*)d_in[3];
    const float* Wp = (const float*)d_in[4];
    const float* bp = (const float*)d_in[5];
    float* out = (float*)d_out;

    (void)in_sizes; (void)n_in; (void)out_size;

    // 1) fused QKV projection (mma.sync tf32)
    qkv_mma_kernel<<<dim3(HH, BS / 128), 256>>>(x, Wq, Wk, Wv);

    // 2) flash attention (fp32)
    cudaFuncSetAttribute(attn_kernel,
                         cudaFuncAttributeMaxDynamicSharedMemorySize,
                         ATT_SMEM_BYTES);
    attn_kernel<<<dim3(SS / 128, BB * HH), 256, ATT_SMEM_BYTES>>>();

    // 3) output projection + bias (mma.sync tf32)
    proj_mma_kernel<<<dim3(EE / 128, BS / 128), 256>>>(Wp, bp, out);
}

// round 6
// speedup vs baseline: 2.5282x; 1.8681x over previous
#include <cuda_runtime.h>
#include <cstdint>
#include <math.h>

// Problem dims (fixed by the reference)
#define BB 8
#define SS 2048
#define EE 512
#define HH 8
#define DD 64
#define BS (BB*SS)          // 16384 rows

// Scratch: q,k,v,att in [B,H,S,D] layout (32 MiB each)
__device__ float g_q[BB*HH*SS*DD];
__device__ float g_k[BB*HH*SS*DD];
__device__ float g_v[BB*HH*SS*DD];
__device__ float g_att[BB*HH*SS*DD];

static __device__ __forceinline__ uint32_t cvt_tf32(float f) {
    uint32_t r; asm("cvt.rna.tf32.f32 %0, %1;" : "=r"(r) : "f"(f)); return r;
}

// m16n8k8 tf32 mma.sync (baseline PTX — no sm_103a-only features)
#define MMA_TF32(c, a, b) \
    asm volatile("mma.sync.aligned.m16n8k8.row.col.f32.tf32.tf32.f32 " \
        "{%0,%1,%2,%3}, {%4,%5,%6,%7}, {%8,%9}, {%0,%1,%2,%3};" \
        : "+f"((c)[0]), "+f"((c)[1]), "+f"((c)[2]), "+f"((c)[3]) \
        : "r"((a)[0]), "r"((a)[1]), "r"((a)[2]), "r"((a)[3]), \
          "r"((b)[0]), "r"((b)[1]))

// ===========================================================================
// Kernel 1: fused QKV projection via mma.sync tf32 (unchanged from R5).
// ===========================================================================
__global__ __launch_bounds__(256, 1)
void qkv_mma_kernel(const float* __restrict__ x,
                    const float* __restrict__ Wq,
                    const float* __restrict__ Wk,
                    const float* __restrict__ Wv)
{
    __shared__ uint32_t Xs[128 * 36];     // 18432 B
    __shared__ uint32_t Ws[32 * 200];     // 25600 B

    const int tid  = threadIdx.x;
    const int wid  = tid >> 5;
    const int lane = tid & 31;
    const int h  = blockIdx.x;
    const int m0 = blockIdx.y * 128;
    const int wm = wid >> 2;              // 0..1
    const int wn = wid & 3;               // 0..3
    const int g   = lane >> 2;            // 0..7
    const int tig = lane & 3;             // 0..3

    const float* Wt0 = Wq + (size_t)h * EE * DD;
    const float* Wt1 = Wk + (size_t)h * EE * DD;
    const float* Wt2 = Wv + (size_t)h * EE * DD;

    float acc[4][6][4];
    #pragma unroll
    for (int mi = 0; mi < 4; mi++)
        #pragma unroll
        for (int ni = 0; ni < 6; ni++)
            #pragma unroll
            for (int j = 0; j < 4; j++) acc[mi][ni][j] = 0.f;

    for (int c = 0; c < 16; c++) {
        const int k0 = c * 32;
        __syncthreads();
        #pragma unroll
        for (int i = 0; i < 4; i++) {
            const int idx = tid + 256 * i;
            const int row = idx >> 3, c4 = idx & 7;
            float4 gv = *(const float4*)&x[(size_t)(m0 + row) * EE + k0 + c4 * 4];
            uint4 t;
            t.x = cvt_tf32(gv.x); t.y = cvt_tf32(gv.y);
            t.z = cvt_tf32(gv.z); t.w = cvt_tf32(gv.w);
            *(uint4*)&Xs[row * 36 + c4 * 4] = t;
        }
        #pragma unroll
        for (int i = 0; i < 6; i++) {
            const int idx = tid + 256 * i;
            const int t  = idx >> 9;
            const int rem = idx & 511;
            const int e  = rem >> 4;
            const int d4 = rem & 15;
            const float* Wp = (t == 0) ? Wt0 : (t == 1) ? Wt1 : Wt2;
            float4 gv = *(const float4*)&Wp[(size_t)(k0 + e) * DD + d4 * 4];
            uint4 tt;
            tt.x = cvt_tf32(gv.x); tt.y = cvt_tf32(gv.y);
            tt.z = cvt_tf32(gv.z); tt.w = cvt_tf32(gv.w);
            *(uint4*)&Ws[e * 200 + t * 64 + d4 * 4] = tt;
        }
        __syncthreads();

        #pragma unroll
        for (int s = 0; s < 4; s++) {
            const int kk = s * 8;
            uint32_t a[4][4];
            #pragma unroll
            for (int mi = 0; mi < 4; mi++) {
                const int mb = wm * 64 + mi * 16;
                a[mi][0] = Xs[(mb + g    ) * 36 + kk + tig];
                a[mi][1] = Xs[(mb + g + 8) * 36 + kk + tig];
                a[mi][2] = Xs[(mb + g    ) * 36 + kk + tig + 4];
                a[mi][3] = Xs[(mb + g + 8) * 36 + kk + tig + 4];
            }
            uint32_t b[6][2];
            #pragma unroll
            for (int ni = 0; ni < 6; ni++) {
                const int nb = wn * 48 + ni * 8;
                b[ni][0] = Ws[(kk + tig    ) * 200 + nb + g];
                b[ni][1] = Ws[(kk + tig + 4) * 200 + nb + g];
            }
            #pragma unroll
            for (int mi = 0; mi < 4; mi++)
                #pragma unroll
                for (int ni = 0; ni < 6; ni++)
                    MMA_TF32(acc[mi][ni], a[mi], b[ni]);
        }
    }

    #pragma unroll
    for (int mi = 0; mi < 4; mi++) {
        const int m1 = m0 + wm * 64 + mi * 16 + g;
        const int b = m1 >> 11, s1 = m1 & 2047;
        #pragma unroll
        for (int ni = 0; ni < 6; ni++) {
            const int colg = wn * 48 + ni * 8 + 2 * tig;
            const int tt = colg >> 6;
            const int d  = colg & 63;
            float* dst = (tt == 0) ? g_q : (tt == 1) ? g_k : g_v;
            const size_t base = (((size_t)(b * HH + h)) * SS + s1) * DD + d;
            *(float2*)&dst[base] = make_float2(acc[mi][ni][0], acc[mi][ni][1]);
            *(float2*)&dst[base + 8 * DD] = make_float2(acc[mi][ni][2], acc[mi][ni][3]);
        }
    }
}

// ===========================================================================
// Kernel 2: flash attention via mma.sync tf32.
// CTA = 128 q-rows, k-tiles of 64.  8 warps x 16 q-rows each; every warp
// spans all 64 keys, so softmax is warp-local (quad shfl).
// SMEM (uint32 words): Qs[128][68] A-side (stride%32==4 -> banks 4g+tig),
// Ks[64d][72key] B-side (stride%32==8 -> banks 8tig+g), Vs[64key][72d],
// Ps[128][68] per-warp-private P staging (C-frag -> A-frag via smem).
// ===========================================================================
#define ATT_Q_OFF 0
#define ATT_K_OFF (128*68)
#define ATT_V_OFF (128*68 + 64*72)
#define ATT_P_OFF (128*68 + 2*64*72)
#define ATT_SMEM_WORDS (128*68 + 2*64*72 + 128*68)
#define ATT_SMEM_BYTES (ATT_SMEM_WORDS * 4)

__global__ __launch_bounds__(256)
void attn_mma_kernel()
{
    extern __shared__ uint32_t smu[];
    uint32_t* Qs = smu + ATT_Q_OFF;
    uint32_t* Ks = smu + ATT_K_OFF;
    uint32_t* Vs = smu + ATT_V_OFF;
    uint32_t* Ps = smu + ATT_P_OFF;

    const int qt = (gridDim.x - 1) - blockIdx.x;   // heavy q-tiles first
    const int bh = blockIdx.y;
    const int tid  = threadIdx.x;
    const int wid  = tid >> 5;
    const int lane = tid & 31;
    const int g   = lane >> 2;
    const int tig = lane & 3;
    const int mb  = wid * 16;            // warp's 16 q-rows

    const float* Qg = g_q + (size_t)bh * SS * DD;
    const float* Kg = g_k + (size_t)bh * SS * DD;
    const float* Vg = g_v + (size_t)bh * SS * DD;

    // Load Q tile (128x64) -> tf32, stride 68
    {
        const int row = tid >> 1;
        const int dbase = (tid & 1) * 32;
        #pragma unroll
        for (int it = 0; it < 8; it++) {
            const int d0 = dbase + it * 4;
            float4 gv = *(const float4*)&Qg[(size_t)(qt * 128 + row) * DD + d0];
            uint4 t;
            t.x = cvt_tf32(gv.x); t.y = cvt_tf32(gv.y);
            t.z = cvt_tf32(gv.z); t.w = cvt_tf32(gv.w);
            *(uint4*)&Qs[row * 68 + d0] = t;
        }
    }

    float o[8][4];
    #pragma unroll
    for (int ni = 0; ni < 8; ni++)
        #pragma unroll
        for (int j = 0; j < 4; j++) o[ni][j] = 0.f;
    float m0r = -1e30f, m1r = -1e30f, l0 = 0.f, l1 = 0.f;

    const int row0 = qt * 128 + mb + g;       // this thread's even row
    const int njt = 2 * qt + 2;

    for (int jt = 0; jt < njt; jt++) {
        __syncthreads();   // prior iter done with Ks/Vs (and covers Q load at jt=0)
        // K -> Ks[d][key] (transposed), V -> Vs[key][d]; both tf32.
        {
            const int key = tid >> 2;
            #pragma unroll
            for (int it = 0; it < 4; it++) {
                const int d0 = (tid & 3) * 16 + it * 4;
                float4 kv = *(const float4*)&Kg[(size_t)(jt * 64 + key) * DD + d0];
                Ks[(d0+0) * 72 + key] = cvt_tf32(kv.x);
                Ks[(d0+1) * 72 + key] = cvt_tf32(kv.y);
                Ks[(d0+2) * 72 + key] = cvt_tf32(kv.z);
                Ks[(d0+3) * 72 + key] = cvt_tf32(kv.w);
                float4 vv = *(const float4*)&Vg[(size_t)(jt * 64 + key) * DD + d0];
                uint4 t;
                t.x = cvt_tf32(vv.x); t.y = cvt_tf32(vv.y);
                t.z = cvt_tf32(vv.z); t.w = cvt_tf32(vv.w);
                *(uint4*)&Vs[key * 72 + d0] = t;
            }
        }
        __syncthreads();

        // S = Q @ K^T : 16 rows x 64 keys per warp = 8 n8 tiles, 8 ksteps (d).
        float sacc[8][4];
        #pragma unroll
        for (int ni = 0; ni < 8; ni++)
            #pragma unroll
            for (int j = 0; j < 4; j++) sacc[ni][j] = 0.f;

        #pragma unroll
        for (int s = 0; s < 8; s++) {
            const int kk = s * 8;
            uint32_t a[4];
            a[0] = Qs[(mb + g    ) * 68 + kk + tig];
            a[1] = Qs[(mb + g + 8) * 68 + kk + tig];
            a[2] = Qs[(mb + g    ) * 68 + kk + tig + 4];
            a[3] = Qs[(mb + g + 8) * 68 + kk + tig + 4];
            #pragma unroll
            for (int ni = 0; ni < 8; ni++) {
                uint32_t b[2];
                b[0] = Ks[(kk + tig    ) * 72 + ni * 8 + g];
                b[1] = Ks[(kk + tig + 4) * 72 + ni * 8 + g];
                MMA_TF32(sacc[ni], a, b);
            }
        }

        // Scale + causal mask (element-wise; only diagonal-straddling tiles)
        const bool diag = (jt >= 2 * qt);
        #pragma unroll
        for (int ni = 0; ni < 8; ni++) {
            const int col = jt * 64 + ni * 8 + 2 * tig;
            float v0 = sacc[ni][0] * 0.125f;
            float v1 = sacc[ni][1] * 0.125f;
            float v2 = sacc[ni][2] * 0.125f;
            float v3 = sacc[ni][3] * 0.125f;
            if (diag) {
                if (col     > row0)     v0 = -1e30f;
                if (col + 1 > row0)     v1 = -1e30f;
                if (col     > row0 + 8) v2 = -1e30f;
                if (col + 1 > row0 + 8) v3 = -1e30f;
            }
            sacc[ni][0] = v0; sacc[ni][1] = v1;
            sacc[ni][2] = v2; sacc[ni][3] = v3;
        }

        // Online softmax (rows g and g+8; reduce across quad lanes)
        float rmax0 = -1e30f, rmax1 = -1e30f;
        #pragma unroll
        for (int ni = 0; ni < 8; ni++) {
            rmax0 = fmaxf(rmax0, fmaxf(sacc[ni][0], sacc[ni][1]));
            rmax1 = fmaxf(rmax1, fmaxf(sacc[ni][2], sacc[ni][3]));
        }
        rmax0 = fmaxf(rmax0, __shfl_xor_sync(0xffffffffu, rmax0, 1));
        rmax0 = fmaxf(rmax0, __shfl_xor_sync(0xffffffffu, rmax0, 2));
        rmax1 = fmaxf(rmax1, __shfl_xor_sync(0xffffffffu, rmax1, 1));
        rmax1 = fmaxf(rmax1, __shfl_xor_sync(0xffffffffu, rmax1, 2));

        const float mn0 = fmaxf(m0r, rmax0);
        const float mn1 = fmaxf(m1r, rmax1);
        const float corr0 = __expf(m0r - mn0);
        const float corr1 = __expf(m1r - mn1);

        float psum0 = 0.f, psum1 = 0.f;
        #pragma unroll
        for (int ni = 0; ni < 8; ni++) {
            float p0 = __expf(sacc[ni][0] - mn0);
            float p1 = __expf(sacc[ni][1] - mn0);
            float p2 = __expf(sacc[ni][2] - mn1);
            float p3 = __expf(sacc[ni][3] - mn1);
            psum0 += p0 + p1; psum1 += p2 + p3;
            // Stage P into per-warp smem (A-frag layout, tf32)
            uint2 w0, w1;
            w0.x = cvt_tf32(p0); w0.y = cvt_tf32(p1);
            w1.x = cvt_tf32(p2); w1.y = cvt_tf32(p3);
            *(uint2*)&Ps[(mb + g    ) * 68 + ni * 8 + 2 * tig] = w0;
            *(uint2*)&Ps[(mb + g + 8) * 68 + ni * 8 + 2 * tig] = w1;
        }
        psum0 += __shfl_xor_sync(0xffffffffu, psum0, 1);
        psum0 += __shfl_xor_sync(0xffffffffu, psum0, 2);
        psum1 += __shfl_xor_sync(0xffffffffu, psum1, 1);
        psum1 += __shfl_xor_sync(0xffffffffu, psum1, 2);

        l0 = l0 * corr0 + psum0;  m0r = mn0;
        l1 = l1 * corr1 + psum1;  m1r = mn1;
        #pragma unroll
        for (int ni = 0; ni < 8; ni++) {
            o[ni][0] *= corr0; o[ni][1] *= corr0;
            o[ni][2] *= corr1; o[ni][3] *= corr1;
        }

        __syncwarp();   // Ps visibility within the warp (warp-private buffer)

        // O += P @ V : contraction over 64 keys = 8 ksteps; 8 d-tiles.
        #pragma unroll
        for (int s = 0; s < 8; s++) {
            const int kk = s * 8;
            uint32_t a[4];
            a[0] = Ps[(mb + g    ) * 68 + kk + tig];
            a[1] = Ps[(mb + g + 8) * 68 + kk + tig];
            a[2] = Ps[(mb + g    ) * 68 + kk + tig + 4];
            a[3] = Ps[(mb + g + 8) * 68 + kk + tig + 4];
            #pragma unroll
            for (int ni = 0; ni < 8; ni++) {
                uint32_t b[2];
                b[0] = Vs[(kk + tig    ) * 72 + ni * 8 + g];
                b[1] = Vs[(kk + tig + 4) * 72 + ni * 8 + g];
                MMA_TF32(o[ni], a, b);
            }
        }
    }

    // Normalize and store to g_att
    float* Og = g_att + (size_t)bh * SS * DD;
    const float inv0 = 1.f / l0;
    const float inv1 = 1.f / l1;
    #pragma unroll
    for (int ni = 0; ni < 8; ni++) {
        const int d = ni * 8 + 2 * tig;
        *(float2*)&Og[(size_t)row0 * DD + d] =
            make_float2(o[ni][0] * inv0, o[ni][1] * inv0);
        *(float2*)&Og[(size_t)(row0 + 8) * DD + d] =
            make_float2(o[ni][2] * inv1, o[ni][3] * inv1);
    }
}

// ===========================================================================
// Kernel 3: output projection via mma.sync tf32 (unchanged from R5).
// ===========================================================================
__global__ __launch_bounds__(256, 2)
void proj_mma_kernel(const float* __restrict__ Wp,
                     const float* __restrict__ bp,
                     float* __restrict__ out)
{
    __shared__ uint32_t Xs[128 * 36];
    __shared__ uint32_t Bs[32 * 136];

    const int tid  = threadIdx.x;
    const int wid  = tid >> 5;
    const int lane = tid & 31;
    const int n0 = blockIdx.x * 128;
    const int m0 = blockIdx.y * 128;
    const int wm = wid >> 2;
    const int wn = wid & 3;
    const int g   = lane >> 2;
    const int tig = lane & 3;

    float acc[4][4][4];
    #pragma unroll
    for (int mi = 0; mi < 4; mi++)
        #pragma unroll
        for (int ni = 0; ni < 4; ni++)
            #pragma unroll
            for (int j = 0; j < 4; j++) acc[mi][ni][j] = 0.f;

    for (int c = 0; c < 16; c++) {
        const int k0 = c * 32;
        const int h = k0 >> 6;
        const int coff = k0 & 63;
        __syncthreads();
        #pragma unroll
        for (int i = 0; i < 4; i++) {
            const int idx = tid + 256 * i;
            const int row = idx >> 3, c4 = idx & 7;
            const int mm = m0 + row;
            const int b = mm >> 11, s = mm & 2047;
            float4 gv = *(const float4*)
                &g_att[(((size_t)(b * HH + h)) * SS + s) * DD + coff + c4 * 4];
            uint4 t;
            t.x = cvt_tf32(gv.x); t.y = cvt_tf32(gv.y);
            t.z = cvt_tf32(gv.z); t.w = cvt_tf32(gv.w);
            *(uint4*)&Xs[row * 36 + c4 * 4] = t;
        }
        #pragma unroll
        for (int i = 0; i < 4; i++) {
            const int idx = tid + 256 * i;
            const int e  = idx >> 5;
            const int n4 = idx & 31;
            float4 gv = *(const float4*)&Wp[(size_t)(k0 + e) * EE + n0 + n4 * 4];
            uint4 t;
            t.x = cvt_tf32(gv.x); t.y = cvt_tf32(gv.y);
            t.z = cvt_tf32(gv.z); t.w = cvt_tf32(gv.w);
            *(uint4*)&Bs[e * 136 + n4 * 4] = t;
        }
        __syncthreads();

        #pragma unroll
        for (int s = 0; s < 4; s++) {
            const int kk = s * 8;
            uint32_t a[4][4];
            #pragma unroll
            for (int mi = 0; mi < 4; mi++) {
                const int mb = wm * 64 + mi * 16;
                a[mi][0] = Xs[(mb + g    ) * 36 + kk + tig];
                a[mi][1] = Xs[(mb + g + 8) * 36 + kk + tig];
                a[mi][2] = Xs[(mb + g    ) * 36 + kk + tig + 4];
                a[mi][3] = Xs[(mb + g + 8) * 36 + kk + tig + 4];
            }
            uint32_t b[4][2];
            #pragma unroll
            for (int ni = 0; ni < 4; ni++) {
                const int nb = wn * 32 + ni * 8;
                b[ni][0] = Bs[(kk + tig    ) * 136 + nb + g];
                b[ni][1] = Bs[(kk + tig + 4) * 136 + nb + g];
            }
            #pragma unroll
            for (int mi = 0; mi < 4; mi++)
                #pragma unroll
                for (int ni = 0; ni < 4; ni++)
                    MMA_TF32(acc[mi][ni], a[mi], b[ni]);
        }
    }

    #pragma unroll
    for (int mi = 0; mi < 4; mi++) {
        const int m1 = m0 + wm * 64 + mi * 16 + g;
        #pragma unroll
        for (int ni = 0; ni < 4; ni++) {
            const int col = n0 + wn * 32 + ni * 8 + 2 * tig;
            float2 bias = *(const float2*)&bp[col];
            *(float2*)&out[(size_t)m1 * EE + col] =
                make_float2(acc[mi][ni][0] + bias.x, acc[mi][ni][1] + bias.y);
            *(float2*)&out[(size_t)(m1 + 8) * EE + col] =
                make_float2(acc[mi][ni][2] + bias.x, acc[mi][ni][3] + bias.y);
        }
    }
}

// ---------------------------------------------------------------------------
extern "C" void kernel_launch(void* const* d_in, const int* in_sizes, int n_in,
                              void* d_out, int out_size)
{
    const float* x  = (const float*)d_in[0];
    const float* Wq = (const float*)d_in[1];
    const float* Wk = (const float*)d_in[2];
    const float* Wv = (const float*)d_in[3];
    const float* Wp = (const float*)d_in[4];
    const float* bp = (const float*)d_in[5];
    float* out = (float*)d_out;

    (void)in_sizes; (void)n_in; (void)out_size;

    // 1) fused QKV projection (mma.sync tf32)
    qkv_mma_kernel<<<dim3(HH, BS / 128), 256>>>(x, Wq, Wk, Wv);

    // 2) flash attention (mma.sync tf32)
    cudaFuncSetAttribute(attn_mma_kernel,
                         cudaFuncAttributeMaxDynamicSharedMemorySize,
                         ATT_SMEM_BYTES);
    attn_mma_kernel<<<dim3(SS / 128, BB * HH), 256, ATT_SMEM_BYTES>>>();

    // 3) output projection + bias (mma.sync tf32)
    proj_mma_kernel<<<dim3(EE / 128, BS / 128), 256>>>(Wp, bp, out);
}

// round 8
// speedup vs baseline: 2.7744x; 1.0974x over previous
#include <cuda_runtime.h>
#include <cstdint>
#include <math.h>

// Problem dims (fixed by the reference)
#define BB 8
#define SS 2048
#define EE 512
#define HH 8
#define DD 64
#define BS (BB*SS)          // 16384 rows

// Scratch: q,k,v,att in [B,H,S,D] layout (32 MiB each)
__device__ float g_q[BB*HH*SS*DD];
__device__ float g_k[BB*HH*SS*DD];
__device__ float g_v[BB*HH*SS*DD];
__device__ float g_att[BB*HH*SS*DD];

static __device__ __forceinline__ uint32_t cvt_tf32(float f) {
    uint32_t r; asm("cvt.rna.tf32.f32 %0, %1;" : "=r"(r) : "f"(f)); return r;
}
static __device__ __forceinline__ uint4 cvt4(float4 g) {
    uint4 t;
    t.x = cvt_tf32(g.x); t.y = cvt_tf32(g.y);
    t.z = cvt_tf32(g.z); t.w = cvt_tf32(g.w);
    return t;
}

// m16n8k8 tf32 mma.sync (baseline PTX — no sm_103a-only features)
#define MMA_TF32(c, a, b) \
    asm volatile("mma.sync.aligned.m16n8k8.row.col.f32.tf32.tf32.f32 " \
        "{%0,%1,%2,%3}, {%4,%5,%6,%7}, {%8,%9}, {%0,%1,%2,%3};" \
        : "+f"((c)[0]), "+f"((c)[1]), "+f"((c)[2]), "+f"((c)[3]) \
        : "r"((a)[0]), "r"((a)[1]), "r"((a)[2]), "r"((a)[3]), \
          "r"((b)[0]), "r"((b)[1]))

// ===========================================================================
// Kernel 1: fused QKV projection via mma.sync tf32 + register prefetch.
// Per CTA: one head h, 128 M-rows, N=192 (q|k|v), K=512 in BK=32 chunks.
// 8 warps as 2(M)x4(N): warp tile 64x48 = 4 m16 x 6 n8.
// ===========================================================================
__global__ __launch_bounds__(256)
void qkv_mma_kernel(const float* __restrict__ x,
                    const float* __restrict__ Wq,
                    const float* __restrict__ Wk,
                    const float* __restrict__ Wv)
{
    __shared__ uint32_t Xs[128 * 36];     // 18432 B
    __shared__ uint32_t Ws[32 * 200];     // 25600 B

    const int tid  = threadIdx.x;
    const int wid  = tid >> 5;
    const int lane = tid & 31;
    const int h  = blockIdx.x;
    const int m0 = blockIdx.y * 128;
    const int wm = wid >> 2;              // 0..1
    const int wn = wid & 3;               // 0..3
    const int g   = lane >> 2;            // 0..7
    const int tig = lane & 3;             // 0..3

    // --- per-thread fixed load coordinates ---
    // X: row_i = (tid>>3) + 32*i, c4 = tid&7
    const int xrow = tid >> 3;
    const int xc4  = tid & 7;
    const float* xptr[4];
    #pragma unroll
    for (int i = 0; i < 4; i++)
        xptr[i] = x + (size_t)(m0 + xrow + 32 * i) * EE + xc4 * 4;

    // W: t_i = i>>1, e_i = (tid>>4) + (i&1)*16, d4 = tid&15
    const int we  = tid >> 4;
    const int wd4 = tid & 15;
    const float* Wsel[3] = { Wq + (size_t)h * EE * DD,
                             Wk + (size_t)h * EE * DD,
                             Wv + (size_t)h * EE * DD };
    const float* wptr[6];
    uint32_t wsoff[6];
    #pragma unroll
    for (int i = 0; i < 6; i++) {
        const int t = i >> 1;
        const int e = we + (i & 1) * 16;
        wptr[i] = Wsel[t] + (size_t)e * DD + wd4 * 4;
        wsoff[i] = e * 200 + t * 64 + wd4 * 4;
    }

    float acc[4][6][4];
    #pragma unroll
    for (int mi = 0; mi < 4; mi++)
        #pragma unroll
        for (int ni = 0; ni < 6; ni++)
            #pragma unroll
            for (int j = 0; j < 4; j++) acc[mi][ni][j] = 0.f;

    // prologue: prefetch chunk 0
    float4 xr[4], wr[6];
    #pragma unroll
    for (int i = 0; i < 4; i++) xr[i] = *(const float4*)xptr[i];
    #pragma unroll
    for (int i = 0; i < 6; i++) wr[i] = *(const float4*)wptr[i];

    for (int c = 0; c < 16; c++) {
        // stage current chunk to smem
        #pragma unroll
        for (int i = 0; i < 4; i++)
            *(uint4*)&Xs[(xrow + 32 * i) * 36 + xc4 * 4] = cvt4(xr[i]);
        #pragma unroll
        for (int i = 0; i < 6; i++)
            *(uint4*)&Ws[wsoff[i]] = cvt4(wr[i]);
        __syncthreads();

        // prefetch next chunk (latency hidden behind the MMA block)
        if (c < 15) {
            #pragma unroll
            for (int i = 0; i < 4; i++)
                xr[i] = *(const float4*)(xptr[i] + (c + 1) * 32);
            #pragma unroll
            for (int i = 0; i < 6; i++)
                wr[i] = *(const float4*)(wptr[i] + (size_t)(c + 1) * 32 * DD);
        }

        #pragma unroll
        for (int s = 0; s < 4; s++) {
            const int kk = s * 8;
            uint32_t a[4][4];
            #pragma unroll
            for (int mi = 0; mi < 4; mi++) {
                const int mb = wm * 64 + mi * 16;
                a[mi][0] = Xs[(mb + g    ) * 36 + kk + tig];
                a[mi][1] = Xs[(mb + g + 8) * 36 + kk + tig];
                a[mi][2] = Xs[(mb + g    ) * 36 + kk + tig + 4];
                a[mi][3] = Xs[(mb + g + 8) * 36 + kk + tig + 4];
            }
            uint32_t b[6][2];
            #pragma unroll
            for (int ni = 0; ni < 6; ni++) {
                const int nb = wn * 48 + ni * 8;
                b[ni][0] = Ws[(kk + tig    ) * 200 + nb + g];
                b[ni][1] = Ws[(kk + tig + 4) * 200 + nb + g];
            }
            #pragma unroll
            for (int mi = 0; mi < 4; mi++)
                #pragma unroll
                for (int ni = 0; ni < 6; ni++)
                    MMA_TF32(acc[mi][ni], a[mi], b[ni]);
        }
        __syncthreads();   // MMA done with smem -> safe to overwrite next iter
    }

    // Epilogue: scatter to g_q / g_k / g_v ([B,H,S,D])
    #pragma unroll
    for (int mi = 0; mi < 4; mi++) {
        const int m1 = m0 + wm * 64 + mi * 16 + g;
        const int b = m1 >> 11, s1 = m1 & 2047;
        #pragma unroll
        for (int ni = 0; ni < 6; ni++) {
            const int colg = wn * 48 + ni * 8 + 2 * tig;
            const int tt = colg >> 6;
            const int d  = colg & 63;
            float* dst = (tt == 0) ? g_q : (tt == 1) ? g_k : g_v;
            const size_t base = (((size_t)(b * HH + h)) * SS + s1) * DD + d;
            *(float2*)&dst[base] = make_float2(acc[mi][ni][0], acc[mi][ni][1]);
            *(float2*)&dst[base + 8 * DD] = make_float2(acc[mi][ni][2], acc[mi][ni][3]);
        }
    }
}

// ===========================================================================
// Kernel 2: flash attention via mma.sync tf32 + K/V register prefetch.
// CTA = 128 q-rows, k-tiles of 64.  8 warps x 16 q-rows each.
// ===========================================================================
#define ATT_Q_OFF 0
#define ATT_K_OFF (128*68)
#define ATT_V_OFF (128*68 + 64*72)
#define ATT_P_OFF (128*68 + 2*64*72)
#define ATT_SMEM_WORDS (128*68 + 2*64*72 + 128*68)
#define ATT_SMEM_BYTES (ATT_SMEM_WORDS * 4)

__global__ __launch_bounds__(256)
void attn_mma_kernel()
{
    extern __shared__ uint32_t smu[];
    uint32_t* Qs = smu + ATT_Q_OFF;
    uint32_t* Ks = smu + ATT_K_OFF;
    uint32_t* Vs = smu + ATT_V_OFF;
    uint32_t* Ps = smu + ATT_P_OFF;

    const int qt = (gridDim.x - 1) - blockIdx.x;   // heavy q-tiles first
    const int bh = blockIdx.y;
    const int tid  = threadIdx.x;
    const int wid  = tid >> 5;
    const int lane = tid & 31;
    const int g   = lane >> 2;
    const int tig = lane & 3;
    const int mb  = wid * 16;            // warp's 16 q-rows

    const float* Qg = g_q + (size_t)bh * SS * DD;
    const float* Kg = g_k + (size_t)bh * SS * DD;
    const float* Vg = g_v + (size_t)bh * SS * DD;

    // Load Q tile (128x64) -> tf32, stride 68
    {
        const int row = tid >> 1;
        const int dbase = (tid & 1) * 32;
        #pragma unroll
        for (int it = 0; it < 8; it++) {
            const int d0 = dbase + it * 4;
            float4 gv = *(const float4*)&Qg[(size_t)(qt * 128 + row) * DD + d0];
            *(uint4*)&Qs[row * 68 + d0] = cvt4(gv);
        }
    }

    float o[8][4];
    #pragma unroll
    for (int ni = 0; ni < 8; ni++)
        #pragma unroll
        for (int j = 0; j < 4; j++) o[ni][j] = 0.f;
    float m0r = -1e30f, m1r = -1e30f, l0 = 0.f, l1 = 0.f;

    const int row0 = qt * 128 + mb + g;       // this thread's even row
    const int njt = 2 * qt + 2;

    // K/V load coords: key = tid>>2, d0_it = (tid&3)*16 + it*4
    const int key = tid >> 2;
    const int db  = (tid & 3) * 16;

    // prologue: prefetch jt = 0
    float4 kr[4], vr[4];
    #pragma unroll
    for (int it = 0; it < 4; it++) {
        kr[it] = *(const float4*)&Kg[(size_t)key * DD + db + it * 4];
        vr[it] = *(const float4*)&Vg[(size_t)key * DD + db + it * 4];
    }

    for (int jt = 0; jt < njt; jt++) {
        __syncthreads();   // prior iter done with Ks/Vs (covers Q at jt=0)
        // stage K (transposed) and V from prefetch regs
        #pragma unroll
        for (int it = 0; it < 4; it++) {
            const int d0 = db + it * 4;
            Ks[(d0+0) * 72 + key] = cvt_tf32(kr[it].x);
            Ks[(d0+1) * 72 + key] = cvt_tf32(kr[it].y);
            Ks[(d0+2) * 72 + key] = cvt_tf32(kr[it].z);
            Ks[(d0+3) * 72 + key] = cvt_tf32(kr[it].w);
            *(uint4*)&Vs[key * 72 + d0] = cvt4(vr[it]);
        }
        __syncthreads();

        // prefetch next k-tile (hidden behind S-MMA + softmax + PV-MMA)
        if (jt + 1 < njt) {
            const size_t kbase = (size_t)((jt + 1) * 64 + key) * DD + db;
            #pragma unroll
            for (int it = 0; it < 4; it++) {
                kr[it] = *(const float4*)&Kg[kbase + it * 4];
                vr[it] = *(const float4*)&Vg[kbase + it * 4];
            }
        }

        // S = Q @ K^T : 16 rows x 64 keys per warp = 8 n8 tiles, 8 ksteps.
        float sacc[8][4];
        #pragma unroll
        for (int ni = 0; ni < 8; ni++)
            #pragma unroll
            for (int j = 0; j < 4; j++) sacc[ni][j] = 0.f;

        #pragma unroll
        for (int s = 0; s < 8; s++) {
            const int kk = s * 8;
            uint32_t a[4];
            a[0] = Qs[(mb + g    ) * 68 + kk + tig];
            a[1] = Qs[(mb + g + 8) * 68 + kk + tig];
            a[2] = Qs[(mb + g    ) * 68 + kk + tig + 4];
            a[3] = Qs[(mb + g + 8) * 68 + kk + tig + 4];
            #pragma unroll
            for (int ni = 0; ni < 8; ni++) {
                uint32_t b[2];
                b[0] = Ks[(kk + tig    ) * 72 + ni * 8 + g];
                b[1] = Ks[(kk + tig + 4) * 72 + ni * 8 + g];
                MMA_TF32(sacc[ni], a, b);
            }
        }

        // Scale + causal mask
        const bool diag = (jt >= 2 * qt);
        #pragma unroll
        for (int ni = 0; ni < 8; ni++) {
            const int col = jt * 64 + ni * 8 + 2 * tig;
            float v0 = sacc[ni][0] * 0.125f;
            float v1 = sacc[ni][1] * 0.125f;
            float v2 = sacc[ni][2] * 0.125f;
            float v3 = sacc[ni][3] * 0.125f;
            if (diag) {
                if (col     > row0)     v0 = -1e30f;
                if (col + 1 > row0)     v1 = -1e30f;
                if (col     > row0 + 8) v2 = -1e30f;
                if (col + 1 > row0 + 8) v3 = -1e30f;
            }
            sacc[ni][0] = v0; sacc[ni][1] = v1;
            sacc[ni][2] = v2; sacc[ni][3] = v3;
        }

        // Online softmax (rows g and g+8; quad shfl reduce)
        float rmax0 = -1e30f, rmax1 = -1e30f;
        #pragma unroll
        for (int ni = 0; ni < 8; ni++) {
            rmax0 = fmaxf(rmax0, fmaxf(sacc[ni][0], sacc[ni][1]));
            rmax1 = fmaxf(rmax1, fmaxf(sacc[ni][2], sacc[ni][3]));
        }
        rmax0 = fmaxf(rmax0, __shfl_xor_sync(0xffffffffu, rmax0, 1));
        rmax0 = fmaxf(rmax0, __shfl_xor_sync(0xffffffffu, rmax0, 2));
        rmax1 = fmaxf(rmax1, __shfl_xor_sync(0xffffffffu, rmax1, 1));
        rmax1 = fmaxf(rmax1, __shfl_xor_sync(0xffffffffu, rmax1, 2));

        const float mn0 = fmaxf(m0r, rmax0);
        const float mn1 = fmaxf(m1r, rmax1);
        const float corr0 = __expf(m0r - mn0);
        const float corr1 = __expf(m1r - mn1);

        float psum0 = 0.f, psum1 = 0.f;
        #pragma unroll
        for (int ni = 0; ni < 8; ni++) {
            float p0 = __expf(sacc[ni][0] - mn0);
            float p1 = __expf(sacc[ni][1] - mn0);
            float p2 = __expf(sacc[ni][2] - mn1);
            float p3 = __expf(sacc[ni][3] - mn1);
            psum0 += p0 + p1; psum1 += p2 + p3;
            uint2 w0, w1;
            w0.x = cvt_tf32(p0); w0.y = cvt_tf32(p1);
            w1.x = cvt_tf32(p2); w1.y = cvt_tf32(p3);
            *(uint2*)&Ps[(mb + g    ) * 68 + ni * 8 + 2 * tig] = w0;
            *(uint2*)&Ps[(mb + g + 8) * 68 + ni * 8 + 2 * tig] = w1;
        }
        psum0 += __shfl_xor_sync(0xffffffffu, psum0, 1);
        psum0 += __shfl_xor_sync(0xffffffffu, psum0, 2);
        psum1 += __shfl_xor_sync(0xffffffffu, psum1, 1);
        psum1 += __shfl_xor_sync(0xffffffffu, psum1, 2);

        l0 = l0 * corr0 + psum0;  m0r = mn0;
        l1 = l1 * corr1 + psum1;  m1r = mn1;
        #pragma unroll
        for (int ni = 0; ni < 8; ni++) {
            o[ni][0] *= corr0; o[ni][1] *= corr0;
            o[ni][2] *= corr1; o[ni][3] *= corr1;
        }

        __syncwarp();   // Ps visibility within the warp (warp-private buffer)

        // O += P @ V
        #pragma unroll
        for (int s = 0; s < 8; s++) {
            const int kk = s * 8;
            uint32_t a[4];
            a[0] = Ps[(mb + g    ) * 68 + kk + tig];
            a[1] = Ps[(mb + g + 8) * 68 + kk + tig];
            a[2] = Ps[(mb + g    ) * 68 + kk + tig + 4];
            a[3] = Ps[(mb + g + 8) * 68 + kk + tig + 4];
            #pragma unroll
            for (int ni = 0; ni < 8; ni++) {
                uint32_t b[2];
                b[0] = Vs[(kk + tig    ) * 72 + ni * 8 + g];
                b[1] = Vs[(kk + tig + 4) * 72 + ni * 8 + g];
                MMA_TF32(o[ni], a, b);
            }
        }
    }

    // Normalize and store to g_att
    float* Og = g_att + (size_t)bh * SS * DD;
    const float inv0 = 1.f / l0;
    const float inv1 = 1.f / l1;
    #pragma unroll
    for (int ni = 0; ni < 8; ni++) {
        const int d = ni * 8 + 2 * tig;
        *(float2*)&Og[(size_t)row0 * DD + d] =
            make_float2(o[ni][0] * inv0, o[ni][1] * inv0);
        *(float2*)&Og[(size_t)(row0 + 8) * DD + d] =
            make_float2(o[ni][2] * inv1, o[ni][3] * inv1);
    }
}

// ===========================================================================
// Kernel 3: output projection via mma.sync tf32 + register prefetch.
// Per CTA: 128 M x 128 N, K=512 in BK=32 chunks.
// ===========================================================================
__global__ __launch_bounds__(256)
void proj_mma_kernel(const float* __restrict__ Wp,
                     const float* __restrict__ bp,
                     float* __restrict__ out)
{
    __shared__ uint32_t Xs[128 * 36];
    __shared__ uint32_t Bs[32 * 136];

    const int tid  = threadIdx.x;
    const int wid  = tid >> 5;
    const int lane = tid & 31;
    const int n0 = blockIdx.x * 128;
    const int m0 = blockIdx.y * 128;
    const int wm = wid >> 2;
    const int wn = wid & 3;
    const int g   = lane >> 2;
    const int tig = lane & 3;

    // A: row_i = (tid>>3)+32i, c4 = tid&7; fixed part of the g_att address
    const int xrow = tid >> 3;
    const int xc4  = tid & 7;
    size_t abase[4];
    #pragma unroll
    for (int i = 0; i < 4; i++) {
        const int mm = m0 + xrow + 32 * i;
        const int b = mm >> 11, s = mm & 2047;
        abase[i] = ((size_t)b * HH * SS + s) * DD + xc4 * 4;
    }
    // B: e_i = (tid>>5)+8i, n4 = tid&31
    const int be  = tid >> 5;
    const int bn4 = tid & 31;

    float acc[4][4][4];
    #pragma unroll
    for (int mi = 0; mi < 4; mi++)
        #pragma unroll
        for (int ni = 0; ni < 4; ni++)
            #pragma unroll
            for (int j = 0; j < 4; j++) acc[mi][ni][j] = 0.f;

    // prologue: prefetch chunk 0 (h=0, coff=0)
    float4 xr[4], br[4];
    #pragma unroll
    for (int i = 0; i < 4; i++)
        xr[i] = *(const float4*)&g_att[abase[i]];
    #pragma unroll
    for (int i = 0; i < 4; i++)
        br[i] = *(const float4*)&Wp[(size_t)(be + 8 * i) * EE + n0 + bn4 * 4];

    for (int c = 0; c < 16; c++) {
        #pragma unroll
        for (int i = 0; i < 4; i++)
            *(uint4*)&Xs[(xrow + 32 * i) * 36 + xc4 * 4] = cvt4(xr[i]);
        #pragma unroll
        for (int i = 0; i < 4; i++)
            *(uint4*)&Bs[(be + 8 * i) * 136 + bn4 * 4] = cvt4(br[i]);
        __syncthreads();

        if (c < 15) {
            const int k1 = (c + 1) * 32;
            const int h1 = k1 >> 6;
            const int coff1 = k1 & 63;
            const size_t hoff = (size_t)h1 * SS * DD + coff1;
            #pragma unroll
            for (int i = 0; i < 4; i++)
                xr[i] = *(const float4*)&g_att[abase[i] + hoff];
            #pragma unroll
            for (int i = 0; i < 4; i++)
                br[i] = *(const float4*)&Wp[(size_t)(k1 + be + 8 * i) * EE + n0 + bn4 * 4];
        }

        #pragma unroll
        for (int s = 0; s < 4; s++) {
            const int kk = s * 8;
            uint32_t a[4][4];
            #pragma unroll
            for (int mi = 0; mi < 4; mi++) {
                const int mb = wm * 64 + mi * 16;
                a[mi][0] = Xs[(mb + g    ) * 36 + kk + tig];
                a[mi][1] = Xs[(mb + g + 8) * 36 + kk + tig];
                a[mi][2] = Xs[(mb + g    ) * 36 + kk + tig + 4];
                a[mi][3] = Xs[(mb + g + 8) * 36 + kk + tig + 4];
            }
            uint32_t b[4][2];
            #pragma unroll
            for (int ni = 0; ni < 4; ni++) {
                const int nb = wn * 32 + ni * 8;
                b[ni][0] = Bs[(kk + tig    ) * 136 + nb + g];
                b[ni][1] = Bs[(kk + tig + 4) * 136 + nb + g];
            }
            #pragma unroll
            for (int mi = 0; mi < 4; mi++)
                #pragma unroll
                for (int ni = 0; ni < 4; ni++)
                    MMA_TF32(acc[mi][ni], a[mi], b[ni]);
        }
        __syncthreads();
    }

    #pragma unroll
    for (int mi = 0; mi < 4; mi++) {
        const int m1 = m0 + wm * 64 + mi * 16 + g;
        #pragma unroll
        for (int ni = 0; ni < 4; ni++) {
            const int col = n0 + wn * 32 + ni * 8 + 2 * tig;
            float2 bias = *(const float2*)&bp[col];
            *(float2*)&out[(size_t)m1 * EE + col] =
                make_float2(acc[mi][ni][0] + bias.x, acc[mi][ni][1] + bias.y);
            *(float2*)&out[(size_t)(m1 + 8) * EE + col] =
                make_float2(acc[mi][ni][2] + bias.x, acc[mi][ni][3] + bias.y);
        }
    }
}

// ---------------------------------------------------------------------------
extern "C" void kernel_launch(void* const* d_in, const int* in_sizes, int n_in,
                              void* d_out, int out_size)
{
    const float* x  = (const float*)d_in[0];
    const float* Wq = (const float*)d_in[1];
    const float* Wk = (const float*)d_in[2];
    const float* Wv = (const float*)d_in[3];
    const float* Wp = (const float*)d_in[4];
    const float* bp = (const float*)d_in[5];
    float* out = (float*)d_out;

    (void)in_sizes; (void)n_in; (void)out_size;

    // 1) fused QKV projection (mma.sync tf32, reg-prefetch pipeline)
    qkv_mma_kernel<<<dim3(HH, BS / 128), 256>>>(x, Wq, Wk, Wv);

    // 2) flash attention (mma.sync tf32, K/V reg-prefetch)
    cudaFuncSetAttribute(attn_mma_kernel,
                         cudaFuncAttributeMaxDynamicSharedMemorySize,
                         ATT_SMEM_BYTES);
    attn_mma_kernel<<<dim3(SS / 128, BB * HH), 256, ATT_SMEM_BYTES>>>();

    // 3) output projection + bias (mma.sync tf32, reg-prefetch pipeline)
    proj_mma_kernel<<<dim3(EE / 128, BS / 128), 256>>>(Wp, bp, out);
}